// round 1
// baseline (speedup 1.0000x reference)
#include <cuda_runtime.h>
#include <cuda_bf16.h>

#define BN_EPS 1e-5f

// ---------------- scratch (device globals; no allocation allowed) ----------
__device__ float g_y1[4 * 128 * 64 * 64];    // conv1 raw (NCHW)
__device__ float g_y4[4 * 128 * 64 * 64];    // conv4 raw (NCHW)
__device__ float g_lk[4 * 64 * 64 * 128];    // BN+ReLU(conv1)  (NHWC)
__device__ float g_lnk[4 * 64 * 64 * 128];   // BN+ReLU(conv4)  (NHWC)
__device__ float g_out0[4 * 128 * 64 * 64];  // trans - lnk     (NCHW)
__device__ float g_y5[4 * 128 * 64 * 64];    // conv5 raw (NCHW)
__device__ float g_scale[3][128];
__device__ float g_shift[3][128];
__device__ float g_pooled[4 * 128];

// ---------------- 3x3 conv as implicit GEMM --------------------------------
// M = 128 (all c_out), N-tile = one pixel row (b,h) of 64 pixels, K = CIN*9.
// 256 threads, BK=16, micro-tile 8x4 per thread.
template <int CIN>
__global__ __launch_bounds__(256) void conv3x3_kernel(
    const float* __restrict__ x,   // [B, CIN, 64, 64]
    const float* __restrict__ w,   // [128, CIN, 3, 3]  (contiguous K per row)
    float* __restrict__ y)         // [B, 128, 64, 64]
{
    const int K = CIN * 9;
    const int bh = blockIdx.x;            // 0..255
    const int b = bh >> 6;
    const int h = bh & 63;
    const int tid = threadIdx.x;
    const int tx = tid & 15;               // pixel group (4 pixels)
    const int ty = tid >> 4;               // c_out group (8 channels)

    __shared__ float As[16][128];          // [k][c_out]
    __shared__ float Bs[16][64];           // [k][pixel]

    float acc[8][4];
#pragma unroll
    for (int i = 0; i < 8; i++)
#pragma unroll
        for (int j = 0; j < 4; j++) acc[i][j] = 0.f;

    const int ar = tid >> 1;               // weight row (c_out) 0..127
    const int ak = (tid & 1) * 8;          // k sub-offset 0 or 8

    for (int kb = 0; kb < K; kb += 16) {
        // ---- load A tile (weights): 128 x 16, float4 x2 per thread ----
        const float* wp = w + ar * K + kb + ak;
        float4 v0 = *(const float4*)(wp);
        float4 v1 = *(const float4*)(wp + 4);
        As[ak + 0][ar] = v0.x; As[ak + 1][ar] = v0.y;
        As[ak + 2][ar] = v0.z; As[ak + 3][ar] = v0.w;
        As[ak + 4][ar] = v1.x; As[ak + 5][ar] = v1.y;
        As[ak + 6][ar] = v1.z; As[ak + 7][ar] = v1.w;

        // ---- load B tile (im2col on the fly): 16 x 64 ----
#pragma unroll
        for (int pass = 0; pass < 4; pass++) {
            int kk = pass * 4 + (tid >> 6);
            int col = tid & 63;
            int k = kb + kk;
            int ci = k / 9;
            int r9 = k - ci * 9;
            int kh = r9 / 3;
            int kw = r9 - kh * 3;
            int hy = h + kh - 1;
            int wx = col + kw - 1;
            float v = 0.f;
            if ((unsigned)hy < 64u && (unsigned)wx < 64u)
                v = x[((b * CIN + ci) * 64 + hy) * 64 + wx];
            Bs[kk][col] = v;
        }
        __syncthreads();

        // ---- compute ----
#pragma unroll
        for (int kk = 0; kk < 16; kk++) {
            float a[8], bb[4];
#pragma unroll
            for (int i = 0; i < 8; i++) a[i] = As[kk][ty * 8 + i];
#pragma unroll
            for (int j = 0; j < 4; j++) bb[j] = Bs[kk][tx * 4 + j];
#pragma unroll
            for (int i = 0; i < 8; i++)
#pragma unroll
                for (int j = 0; j < 4; j++) acc[i][j] = fmaf(a[i], bb[j], acc[i][j]);
        }
        __syncthreads();
    }

    // ---- store (coalesced float4) ----
#pragma unroll
    for (int i = 0; i < 8; i++) {
        int c = ty * 8 + i;
        float4 o = make_float4(acc[i][0], acc[i][1], acc[i][2], acc[i][3]);
        *(float4*)(y + ((b * 128 + c) * 64 + h) * 64 + tx * 4) = o;
    }
}

// ---------------- BN batch stats -> per-channel scale/shift ----------------
__global__ void bn_stats_kernel(const float* __restrict__ y,
                                const float* __restrict__ gamma,
                                const float* __restrict__ beta,
                                float* __restrict__ scale,
                                float* __restrict__ shift)
{
    int c = blockIdx.x;
    int tid = threadIdx.x;
    float s = 0.f, s2 = 0.f;
    for (int b = 0; b < 4; b++) {
        const float* p = y + (b * 128 + c) * 4096;
        for (int i = tid; i < 4096; i += 256) {
            float v = p[i];
            s += v;
            s2 += v * v;
        }
    }
    __shared__ float sh[256], sh2[256];
    sh[tid] = s; sh2[tid] = s2;
    __syncthreads();
    for (int o = 128; o > 0; o >>= 1) {
        if (tid < o) { sh[tid] += sh[tid + o]; sh2[tid] += sh2[tid + o]; }
        __syncthreads();
    }
    if (tid == 0) {
        float mean = sh[0] * (1.f / 16384.f);
        float var  = sh2[0] * (1.f / 16384.f) - mean * mean;
        float sc = gamma[c] * rsqrtf(var + BN_EPS);
        scale[c] = sc;
        shift[c] = beta[c] - mean * sc;
    }
}

// ---------------- BN + ReLU + NCHW -> NHWC transpose ------------------------
__global__ void bn_relu_transpose_kernel(const float* __restrict__ y,
                                         const float* __restrict__ scale,
                                         const float* __restrict__ shift,
                                         float* __restrict__ o)
{
    __shared__ float t[32][33];
    int b = blockIdx.z;
    int c0 = blockIdx.y * 32;
    int p0 = blockIdx.x * 32;
    int txi = threadIdx.x, tyi = threadIdx.y;
#pragma unroll
    for (int r = 0; r < 4; r++) {
        int c = c0 + tyi + r * 8;
        float v = y[(b * 128 + c) * 4096 + p0 + txi];
        v = fmaxf(fmaf(v, scale[c], shift[c]), 0.f);
        t[tyi + r * 8][txi] = v;
    }
    __syncthreads();
#pragma unroll
    for (int r = 0; r < 4; r++) {
        int p = p0 + tyi + r * 8;
        o[(b * 4096 + p) * 128 + c0 + txi] = t[txi][tyi + r * 8];
    }
}

// ---------------- local weighting (9x9) + subtract lnk ---------------------
__global__ __launch_bounds__(128) void local_weight_kernel(
    const float* __restrict__ atten,  // [B,H,W,81]
    const float* __restrict__ lk,     // NHWC
    const float* __restrict__ lnk,    // NHWC
    float* __restrict__ out0)         // NCHW
{
    int bp = blockIdx.x;              // b*4096 + p
    int b = bp >> 12;
    int p = bp & 4095;
    int h = p >> 6;
    int w = p & 63;

    __shared__ float att[81];
    if (threadIdx.x < 81) att[threadIdx.x] = atten[bp * 81 + threadIdx.x];
    __syncthreads();

    int c = threadIdx.x;
    float acc = 0.f;
#pragma unroll
    for (int dh = 0; dh < 9; dh++) {
        int yy = h + dh - 4;
        if ((unsigned)yy >= 64u) continue;
        const float* row = lk + ((b * 64 + yy) * 64) * 128 + c;
#pragma unroll
        for (int dw = 0; dw < 9; dw++) {
            int xx = w + dw - 4;
            if ((unsigned)xx < 64u)
                acc = fmaf(att[dh * 9 + dw], row[xx * 128], acc);
        }
    }
    out0[((b * 128 + c) * 64 + h) * 64 + w] = acc - lnk[bp * 128 + c];
}

// ---------------- BN + ReLU + global average pool ---------------------------
__global__ void pool_bn_relu_kernel(const float* __restrict__ y,
                                    const float* __restrict__ scale,
                                    const float* __restrict__ shift,
                                    float* __restrict__ pooled)
{
    int bc = blockIdx.x;       // b*128 + c
    int c = bc & 127;
    float sc = scale[c], sf = shift[c];
    const float* p = y + bc * 4096;
    float s = 0.f;
    for (int i = threadIdx.x; i < 4096; i += 256)
        s += fmaxf(fmaf(p[i], sc, sf), 0.f);
    __shared__ float sh[256];
    sh[threadIdx.x] = s;
    __syncthreads();
    for (int o = 128; o > 0; o >>= 1) {
        if (threadIdx.x < o) sh[threadIdx.x] += sh[threadIdx.x + o];
        __syncthreads();
    }
    if (threadIdx.x == 0) pooled[bc] = sh[0] * (1.f / 4096.f);
}

// ---------------- FC head ----------------------------------------------------
__global__ void fc_kernel(const float* __restrict__ pooled,
                          const float* __restrict__ fc1w,
                          const float* __restrict__ fc1b,
                          const float* __restrict__ fc2w,
                          const float* __restrict__ fc2b,
                          float* __restrict__ out)
{
    __shared__ float hbuf[4][10];
    int tid = threadIdx.x;
    if (tid < 40) {
        int b = tid / 10, j = tid % 10;
        float s = fc1b[j];
        const float* wr = fc1w + j * 128;
        const float* pr = pooled + b * 128;
        for (int c = 0; c < 128; c++) s = fmaf(wr[c], pr[c], s);
        hbuf[b][j] = s;
    }
    __syncthreads();
    if (tid < 4) {
        float s = fc2b[0];
        for (int j = 0; j < 10; j++) s = fmaf(fc2w[j], hbuf[tid][j], s);
        out[tid] = s;
    }
}

// ---------------- launch ----------------------------------------------------
extern "C" void kernel_launch(void* const* d_in, const int* in_sizes, int n_in,
                              void* d_out, int out_size)
{
    const float* low_key    = (const float*)d_in[0];
    const float* low_nonkey = (const float*)d_in[1];
    const float* atten      = (const float*)d_in[2];
    const float* w1 = (const float*)d_in[3];
    const float* g1 = (const float*)d_in[4];
    const float* b1 = (const float*)d_in[5];
    const float* w4 = (const float*)d_in[6];
    const float* g4 = (const float*)d_in[7];
    const float* b4 = (const float*)d_in[8];
    const float* w5 = (const float*)d_in[9];
    const float* g5 = (const float*)d_in[10];
    const float* b5 = (const float*)d_in[11];
    const float* fc1w = (const float*)d_in[12];
    const float* fc1b = (const float*)d_in[13];
    const float* fc2w = (const float*)d_in[14];
    const float* fc2b = (const float*)d_in[15];
    float* out = (float*)d_out;

    float *y1, *y4, *lk, *lnk, *out0, *y5, *scale, *shift, *pooled;
    cudaGetSymbolAddress((void**)&y1, g_y1);
    cudaGetSymbolAddress((void**)&y4, g_y4);
    cudaGetSymbolAddress((void**)&lk, g_lk);
    cudaGetSymbolAddress((void**)&lnk, g_lnk);
    cudaGetSymbolAddress((void**)&out0, g_out0);
    cudaGetSymbolAddress((void**)&y5, g_y5);
    cudaGetSymbolAddress((void**)&scale, g_scale);
    cudaGetSymbolAddress((void**)&shift, g_shift);
    cudaGetSymbolAddress((void**)&pooled, g_pooled);

    float* scale1 = scale + 0 * 128; float* shift1 = shift + 0 * 128;
    float* scale4 = scale + 1 * 128; float* shift4 = shift + 1 * 128;
    float* scale5 = scale + 2 * 128; float* shift5 = shift + 2 * 128;

    // conv1 / conv4 (the two big GEMMs)
    conv3x3_kernel<1024><<<256, 256>>>(low_key, w1, y1);
    conv3x3_kernel<1024><<<256, 256>>>(low_nonkey, w4, y4);

    // BN stats
    bn_stats_kernel<<<128, 256>>>(y1, g1, b1, scale1, shift1);
    bn_stats_kernel<<<128, 256>>>(y4, g4, b4, scale4, shift4);

    // BN+ReLU + transpose to NHWC
    dim3 tgrid(128, 4, 4), tblk(32, 8);
    bn_relu_transpose_kernel<<<tgrid, tblk>>>(y1, scale1, shift1, lk);
    bn_relu_transpose_kernel<<<tgrid, tblk>>>(y4, scale4, shift4, lnk);

    // local weighting + subtract
    local_weight_kernel<<<16384, 128>>>(atten, lk, lnk, out0);

    // conv5
    conv3x3_kernel<128><<<256, 256>>>(out0, w5, y5);
    bn_stats_kernel<<<128, 256>>>(y5, g5, b5, scale5, shift5);

    // pool + fc
    pool_bn_relu_kernel<<<512, 256>>>(y5, scale5, shift5, pooled);
    fc_kernel<<<1, 64>>>(pooled, fc1w, fc1b, fc2w, fc2b, out);
}

// round 3
// speedup vs baseline: 1.8867x; 1.8867x over previous
#include <cuda_runtime.h>
#include <cuda_bf16.h>
#include <cstdint>

#define BN_EPS 1e-5f

// ---------------- scratch (device globals; no allocation allowed) ----------
__device__ float g_y1[4 * 128 * 64 * 64];            // conv1 raw (NCHW)
__device__ float g_y4[4 * 128 * 64 * 64];            // conv4 raw (NCHW)
__device__ float g_y5[4 * 128 * 64 * 64];            // conv5 raw (NCHW)
__device__ float g_lk[4 * 64 * 64 * 128];            // BN+ReLU(conv1) NHWC fp32
__device__ float g_lnk[4 * 64 * 64 * 128];           // BN+ReLU(conv4) NHWC fp32
__device__ __nv_bfloat16 g_xk_h[4 * 64 * 64 * 1024]; // low_key NHWC hi
__device__ __nv_bfloat16 g_xk_l[4 * 64 * 64 * 1024]; // low_key NHWC lo
__device__ __nv_bfloat16 g_xn_h[4 * 64 * 64 * 1024];
__device__ __nv_bfloat16 g_xn_l[4 * 64 * 64 * 1024];
__device__ __nv_bfloat16 g_w1_h[128 * 9216];         // reordered [c][pos*1024+ci]
__device__ __nv_bfloat16 g_w1_l[128 * 9216];
__device__ __nv_bfloat16 g_w4_h[128 * 9216];
__device__ __nv_bfloat16 g_w4_l[128 * 9216];
__device__ __nv_bfloat16 g_w5_h[128 * 1152];
__device__ __nv_bfloat16 g_w5_l[128 * 1152];
__device__ __nv_bfloat16 g_o0_h[4 * 64 * 64 * 128];  // (trans - lnk) NHWC hi
__device__ __nv_bfloat16 g_o0_l[4 * 64 * 64 * 128];
__device__ float g_scale[3][128];
__device__ float g_shift[3][128];
__device__ float g_pooled[4 * 128];

// ======================= PTX helpers (baseline ISA only) ====================
__device__ __forceinline__ uint32_t smem_u32(const void* p) {
    uint32_t a;
    asm("{ .reg .u64 t; cvta.to.shared.u64 t, %1; cvt.u32.u64 %0, t; }" : "=r"(a) : "l"(p));
    return a;
}
__device__ __forceinline__ void cp16(uint32_t dst, const void* src, int sz) {
    asm volatile("cp.async.cg.shared.global [%0], [%1], 16, %2;\n"
                 :: "r"(dst), "l"(src), "r"(sz));
}
__device__ __forceinline__ void ldsm_x4(uint32_t& r0, uint32_t& r1, uint32_t& r2,
                                        uint32_t& r3, uint32_t addr) {
    asm volatile("ldmatrix.sync.aligned.m8n8.x4.shared.b16 {%0,%1,%2,%3}, [%4];"
                 : "=r"(r0), "=r"(r1), "=r"(r2), "=r"(r3) : "r"(addr));
}
__device__ __forceinline__ void mma16816(float* d, const uint32_t* a, const uint32_t* b) {
    asm volatile(
        "mma.sync.aligned.m16n8k16.row.col.f32.bf16.bf16.f32 "
        "{%0,%1,%2,%3}, {%4,%5,%6,%7}, {%8,%9}, {%0,%1,%2,%3};"
        : "+f"(d[0]), "+f"(d[1]), "+f"(d[2]), "+f"(d[3])
        : "r"(a[0]), "r"(a[1]), "r"(a[2]), "r"(a[3]), "r"(b[0]), "r"(b[1]));
}

// ======================= conv GEMM (mma.sync bf16 hi/lo split) ==============
// CTA: M=128 (c_out) x N=128 pixels (2 rows x 64) ; K-chunk = 32 (one tap,
// 32 in-channels). 3 products (HH, HL, LH). 8 warps as 4(M) x 2(N),
// warp tile 32x64. SMEM pitch 80B (conflict-free ldmatrix), double buffered.
// Stage layout: A_h[0,10240) A_l[10240,20480) B_h[20480,30720) B_l[30720,40960)
#define PITCH 80
#define STG_AL 10240
#define STG_BH 20480
#define STG_BL 30720
#define STAGE_SZ 40960

template <int CIN>
__device__ __forceinline__ void load_stage(
    uint32_t sb,
    const __nv_bfloat16* __restrict__ wh, const __nv_bfloat16* __restrict__ wl,
    const __nv_bfloat16* __restrict__ xh, const __nv_bfloat16* __restrict__ xl,
    int iter, int b, int h0, int tid)
{
    const int K = CIN * 9;
    int pos = iter % 9, cic = iter / 9;      // tap-minor for cross-CTA L2 reuse
    int kh = pos / 3, kw = pos - 3 * kh;
    int k0 = pos * CIN + cic * 32;

    // A: 128 rows x 64B x 2 halves = 1024 chunks of 16B; 4/thread
#pragma unroll
    for (int u = 0; u < 4; u++) {
        int idx = tid * 4 + u;
        int hl = idx >> 9, rem = idx & 511;
        int row = rem >> 2, c16 = rem & 3;
        const __nv_bfloat16* src = (hl ? wl : wh) + row * K + k0 + c16 * 8;
        cp16(sb + hl * STG_AL + row * PITCH + c16 * 16, src, 16);
    }
    // B: 128 pixels x 64B x 2 halves = 1024 chunks; 4/thread
#pragma unroll
    for (int u = 0; u < 4; u++) {
        int idx = tid * 4 + u;
        int hl = idx >> 9, rem = idx & 511;
        int px = rem >> 2, c16 = rem & 3;
        int r = px >> 6, ww = px & 63;
        int y = h0 + r + kh - 1;
        int xw = ww + kw - 1;
        bool ok = ((unsigned)y < 64u) && ((unsigned)xw < 64u);
        int yc = ok ? y : 0, xc = ok ? xw : 0;
        const __nv_bfloat16* src =
            (hl ? xl : xh) + ((size_t)((b * 64 + yc) * 64 + xc)) * CIN + cic * 32 + c16 * 8;
        cp16(sb + STG_BH + hl * STG_AL + px * PITCH + c16 * 16, src, ok ? 16 : 0);
    }
}

template <int CIN, int DUAL>
__global__ __launch_bounds__(256, 2) void conv_mma_kernel(
    const __nv_bfloat16* __restrict__ xh0, const __nv_bfloat16* __restrict__ xl0,
    const __nv_bfloat16* __restrict__ wh0, const __nv_bfloat16* __restrict__ wl0,
    float* __restrict__ y0,
    const __nv_bfloat16* __restrict__ xh1, const __nv_bfloat16* __restrict__ xl1,
    const __nv_bfloat16* __restrict__ wh1, const __nv_bfloat16* __restrict__ wl1,
    float* __restrict__ y1p)
{
    extern __shared__ char smem[];
    const uint32_t sbase = smem_u32(smem);
    const int tid = threadIdx.x;
    const int wid = tid >> 5;
    const int lane = tid & 31;

    int bx = blockIdx.x;
    int sel = DUAL ? (bx >> 7) : 0;
    int t = DUAL ? (bx & 127) : bx;
    int b = t >> 5;
    int h0 = (t & 31) * 2;

    const __nv_bfloat16* xh = sel ? xh1 : xh0;
    const __nv_bfloat16* xl = sel ? xl1 : xl0;
    const __nv_bfloat16* wh = sel ? wh1 : wh0;
    const __nv_bfloat16* wl = sel ? wl1 : wl0;
    float* y = sel ? y1p : y0;

    const int mi = wid & 3;     // M block: 32 rows
    const int ni = wid >> 2;    // N block: 64 pixels
    const int m0 = mi * 32;
    const int n0 = ni * 64;

    float acc[2][8][4];
#pragma unroll
    for (int a = 0; a < 2; a++)
#pragma unroll
        for (int j = 0; j < 8; j++)
#pragma unroll
            for (int e = 0; e < 4; e++) acc[a][j][e] = 0.f;

    constexpr int NIT = 9 * (CIN / 32);
    const uint32_t stage0 = sbase;
    const uint32_t stage1 = sbase + STAGE_SZ;

    load_stage<CIN>(stage0, wh, wl, xh, xl, 0, b, h0, tid);
    asm volatile("cp.async.commit_group;" ::: "memory");
    load_stage<CIN>(stage1, wh, wl, xh, xl, 1, b, h0, tid);
    asm volatile("cp.async.commit_group;" ::: "memory");

    // precomputed ldmatrix lane offsets
    const uint32_t a_off = (uint32_t)((lane & 15) * PITCH + (lane >> 4) * 16);
    const uint32_t b_off = a_off;

    for (int i = 0; i < NIT; i++) {
        uint32_t st = (i & 1) ? stage1 : stage0;

        if (i + 1 < NIT) asm volatile("cp.async.wait_group 1;" ::: "memory");
        else             asm volatile("cp.async.wait_group 0;" ::: "memory");
        __syncthreads();

#pragma unroll
        for (int p = 0; p < 3; p++) {
            uint32_t sA = st + (p == 2 ? STG_AL : 0);
            uint32_t sB = st + STG_BH + (p == 1 ? STG_AL : 0);
#pragma unroll
            for (int s = 0; s < 2; s++) {   // two k16 steps in k-chunk 32
                uint32_t af[2][4];
#pragma unroll
                for (int tt = 0; tt < 2; tt++)
                    ldsm_x4(af[tt][0], af[tt][1], af[tt][2], af[tt][3],
                            sA + (m0 + tt * 16) * PITCH + s * 32 + a_off);
                uint32_t bf[4][4];
#pragma unroll
                for (int q = 0; q < 4; q++)
                    ldsm_x4(bf[q][0], bf[q][1], bf[q][2], bf[q][3],
                            sB + (n0 + q * 16) * PITCH + s * 32 + b_off);
#pragma unroll
                for (int tt = 0; tt < 2; tt++)
#pragma unroll
                    for (int q = 0; q < 4; q++) {
                        uint32_t b0[2] = { bf[q][0], bf[q][2] };   // n8 tile 0
                        uint32_t b1[2] = { bf[q][1], bf[q][3] };   // n8 tile 1
                        mma16816(acc[tt][q * 2 + 0], af[tt], b0);
                        mma16816(acc[tt][q * 2 + 1], af[tt], b1);
                    }
            }
        }
        __syncthreads();
        if (i + 2 < NIT) {
            load_stage<CIN>(st, wh, wl, xh, xl, i + 2, b, h0, tid);
            asm volatile("cp.async.commit_group;" ::: "memory");
        }
    }

    // epilogue: D frag mapping: row = groupID (+8), col = 2*tig (+1)
    const int gid = lane >> 2;
    const int tig = lane & 3;
#pragma unroll
    for (int tt = 0; tt < 2; tt++) {
        int r0 = m0 + tt * 16 + gid;
#pragma unroll
        for (int j = 0; j < 8; j++) {
            int col = n0 + j * 8 + tig * 2;
            float* d0 = y + (size_t)(b * 128 + r0) * 4096 + h0 * 64 + col;
            float* d1 = y + (size_t)(b * 128 + r0 + 8) * 4096 + h0 * 64 + col;
            d0[0] = acc[tt][j][0]; d0[1] = acc[tt][j][1];
            d1[0] = acc[tt][j][2]; d1[1] = acc[tt][j][3];
        }
    }
}

// ======================= prep kernels =======================================
// weights: [c_out][ci][kh][kw] -> [c_out][pos*CIN+ci], bf16 hi/lo split
__global__ void prep_w_kernel(const float* __restrict__ w,
                              __nv_bfloat16* __restrict__ wh,
                              __nv_bfloat16* __restrict__ wl, int CIN)
{
    int K = CIN * 9;
    int total = 128 * K;
    for (int i = blockIdx.x * blockDim.x + threadIdx.x; i < total;
         i += gridDim.x * blockDim.x) {
        int c = i / K, k = i - c * K;
        int pos = k / CIN, ci = k - pos * CIN;
        float v = w[(c * CIN + ci) * 9 + pos];
        __nv_bfloat16 h = __float2bfloat16(v);
        wh[i] = h;
        wl[i] = __float2bfloat16(v - __bfloat162float(h));
    }
}

// x: NCHW fp32 -> NHWC bf16 hi/lo
__global__ void prep_x_kernel(const float* __restrict__ x,
                              __nv_bfloat16* __restrict__ xh,
                              __nv_bfloat16* __restrict__ xl)
{
    __shared__ float ttile[32][33];
    int bh = blockIdx.z;
    int b = bh >> 6, h = bh & 63;
    int ciT = blockIdx.y * 32, wT = blockIdx.x * 32;
    int tx = threadIdx.x, ty = threadIdx.y;
#pragma unroll
    for (int r = 0; r < 4; r++) {
        int ci = ciT + ty + r * 8;
        ttile[ty + r * 8][tx] = x[((size_t)(b * 1024 + ci) * 64 + h) * 64 + wT + tx];
    }
    __syncthreads();
#pragma unroll
    for (int r = 0; r < 4; r++) {
        int w = wT + ty + r * 8;
        float v = ttile[tx][ty + r * 8];
        __nv_bfloat16 hi = __float2bfloat16(v);
        size_t o = ((size_t)(b * 64 + h) * 64 + w) * 1024 + ciT + tx;
        xh[o] = hi;
        xl[o] = __float2bfloat16(v - __bfloat162float(hi));
    }
}

// ======================= BN / elementwise chain =============================
__global__ void bn_stats_kernel(const float* __restrict__ y,
                                const float* __restrict__ gamma,
                                const float* __restrict__ beta,
                                float* __restrict__ scale,
                                float* __restrict__ shift)
{
    int c = blockIdx.x;
    int tid = threadIdx.x;
    float s = 0.f, s2 = 0.f;
    for (int b = 0; b < 4; b++) {
        const float4* p = (const float4*)(y + (size_t)(b * 128 + c) * 4096);
        for (int i = tid; i < 1024; i += 256) {
            float4 v = p[i];
            s  += v.x + v.y + v.z + v.w;
            s2 += v.x * v.x + v.y * v.y + v.z * v.z + v.w * v.w;
        }
    }
    __shared__ float sh[256], sh2[256];
    sh[tid] = s; sh2[tid] = s2;
    __syncthreads();
    for (int o = 128; o > 0; o >>= 1) {
        if (tid < o) { sh[tid] += sh[tid + o]; sh2[tid] += sh2[tid + o]; }
        __syncthreads();
    }
    if (tid == 0) {
        float mean = sh[0] * (1.f / 16384.f);
        float var  = sh2[0] * (1.f / 16384.f) - mean * mean;
        float sc = gamma[c] * rsqrtf(var + BN_EPS);
        scale[c] = sc;
        shift[c] = beta[c] - mean * sc;
    }
}

__global__ void bn_relu_transpose_kernel(const float* __restrict__ y,
                                         const float* __restrict__ scale,
                                         const float* __restrict__ shift,
                                         float* __restrict__ o)
{
    __shared__ float ttile[32][33];
    int b = blockIdx.z;
    int c0 = blockIdx.y * 32;
    int p0 = blockIdx.x * 32;
    int tx = threadIdx.x, ty = threadIdx.y;
#pragma unroll
    for (int r = 0; r < 4; r++) {
        int c = c0 + ty + r * 8;
        float v = y[(size_t)(b * 128 + c) * 4096 + p0 + tx];
        v = fmaxf(fmaf(v, scale[c], shift[c]), 0.f);
        ttile[ty + r * 8][tx] = v;
    }
    __syncthreads();
#pragma unroll
    for (int r = 0; r < 4; r++) {
        int p = p0 + ty + r * 8;
        o[(size_t)(b * 4096 + p) * 128 + c0 + tx] = ttile[tx][ty + r * 8];
    }
}

// local weighting + subtract lnk; output as NHWC bf16 hi/lo (conv5 B operand)
__global__ __launch_bounds__(128) void local_weight_kernel(
    const float* __restrict__ atten,  // [B,H,W,81]
    const float* __restrict__ lk,     // NHWC fp32
    const float* __restrict__ lnk,    // NHWC fp32
    __nv_bfloat16* __restrict__ oh,
    __nv_bfloat16* __restrict__ ol)
{
    int bp = blockIdx.x;
    int b = bp >> 12;
    int p = bp & 4095;
    int h = p >> 6;
    int w = p & 63;

    __shared__ float att[81];
    if (threadIdx.x < 81) att[threadIdx.x] = atten[(size_t)bp * 81 + threadIdx.x];
    __syncthreads();

    int c = threadIdx.x;
    float acc = 0.f;
#pragma unroll
    for (int dh = 0; dh < 9; dh++) {
        int yy = h + dh - 4;
        if ((unsigned)yy >= 64u) continue;
        const float* row = lk + (size_t)((b * 64 + yy) * 64) * 128 + c;
#pragma unroll
        for (int dw = 0; dw < 9; dw++) {
            int xx = w + dw - 4;
            if ((unsigned)xx < 64u)
                acc = fmaf(att[dh * 9 + dw], row[(size_t)xx * 128], acc);
        }
    }
    float v = acc - lnk[(size_t)bp * 128 + c];
    __nv_bfloat16 hi = __float2bfloat16(v);
    oh[(size_t)bp * 128 + c] = hi;
    ol[(size_t)bp * 128 + c] = __float2bfloat16(v - __bfloat162float(hi));
}

__global__ void pool_bn_relu_kernel(const float* __restrict__ y,
                                    const float* __restrict__ scale,
                                    const float* __restrict__ shift,
                                    float* __restrict__ pooled)
{
    int bc = blockIdx.x;
    int c = bc & 127;
    float sc = scale[c], sf = shift[c];
    const float* p = y + (size_t)bc * 4096;
    float s = 0.f;
    for (int i = threadIdx.x; i < 4096; i += 256)
        s += fmaxf(fmaf(p[i], sc, sf), 0.f);
    __shared__ float sh[256];
    sh[threadIdx.x] = s;
    __syncthreads();
    for (int o = 128; o > 0; o >>= 1) {
        if (threadIdx.x < o) sh[threadIdx.x] += sh[threadIdx.x + o];
        __syncthreads();
    }
    if (threadIdx.x == 0) pooled[bc] = sh[0] * (1.f / 4096.f);
}

__global__ void fc_kernel(const float* __restrict__ pooled,
                          const float* __restrict__ fc1w,
                          const float* __restrict__ fc1b,
                          const float* __restrict__ fc2w,
                          const float* __restrict__ fc2b,
                          float* __restrict__ out)
{
    __shared__ float hbuf[4][10];
    int tid = threadIdx.x;
    if (tid < 40) {
        int b = tid / 10, j = tid % 10;
        float s = fc1b[j];
        const float* wr = fc1w + j * 128;
        const float* pr = pooled + b * 128;
        for (int c = 0; c < 128; c++) s = fmaf(wr[c], pr[c], s);
        hbuf[b][j] = s;
    }
    __syncthreads();
    if (tid < 4) {
        float s = fc2b[0];
        for (int j = 0; j < 10; j++) s = fmaf(fc2w[j], hbuf[tid][j], s);
        out[tid] = s;
    }
}

// ======================= launch =============================================
extern "C" void kernel_launch(void* const* d_in, const int* in_sizes, int n_in,
                              void* d_out, int out_size)
{
    const float* low_key    = (const float*)d_in[0];
    const float* low_nonkey = (const float*)d_in[1];
    const float* atten      = (const float*)d_in[2];
    const float* w1 = (const float*)d_in[3];
    const float* g1 = (const float*)d_in[4];
    const float* b1 = (const float*)d_in[5];
    const float* w4 = (const float*)d_in[6];
    const float* g4 = (const float*)d_in[7];
    const float* b4 = (const float*)d_in[8];
    const float* w5 = (const float*)d_in[9];
    const float* g5 = (const float*)d_in[10];
    const float* b5 = (const float*)d_in[11];
    const float* fc1w = (const float*)d_in[12];
    const float* fc1b = (const float*)d_in[13];
    const float* fc2w = (const float*)d_in[14];
    const float* fc2b = (const float*)d_in[15];
    float* out = (float*)d_out;

    float *y1, *y4, *y5, *lk, *lnk, *scale, *shift, *pooled;
    __nv_bfloat16 *xkh, *xkl, *xnh, *xnl, *w1h, *w1l, *w4h, *w4l, *w5h, *w5l, *o0h, *o0l;
    cudaGetSymbolAddress((void**)&y1, g_y1);
    cudaGetSymbolAddress((void**)&y4, g_y4);
    cudaGetSymbolAddress((void**)&y5, g_y5);
    cudaGetSymbolAddress((void**)&lk, g_lk);
    cudaGetSymbolAddress((void**)&lnk, g_lnk);
    cudaGetSymbolAddress((void**)&xkh, g_xk_h);
    cudaGetSymbolAddress((void**)&xkl, g_xk_l);
    cudaGetSymbolAddress((void**)&xnh, g_xn_h);
    cudaGetSymbolAddress((void**)&xnl, g_xn_l);
    cudaGetSymbolAddress((void**)&w1h, g_w1_h);
    cudaGetSymbolAddress((void**)&w1l, g_w1_l);
    cudaGetSymbolAddress((void**)&w4h, g_w4_h);
    cudaGetSymbolAddress((void**)&w4l, g_w4_l);
    cudaGetSymbolAddress((void**)&w5h, g_w5_h);
    cudaGetSymbolAddress((void**)&w5l, g_w5_l);
    cudaGetSymbolAddress((void**)&o0h, g_o0_h);
    cudaGetSymbolAddress((void**)&o0l, g_o0_l);
    cudaGetSymbolAddress((void**)&scale, g_scale);
    cudaGetSymbolAddress((void**)&shift, g_shift);
    cudaGetSymbolAddress((void**)&pooled, g_pooled);

    float* scale1 = scale + 0 * 128; float* shift1 = shift + 0 * 128;
    float* scale4 = scale + 1 * 128; float* shift4 = shift + 1 * 128;
    float* scale5 = scale + 2 * 128; float* shift5 = shift + 2 * 128;

    const int CONV_SMEM = 2 * STAGE_SZ;  // 81920
    cudaFuncSetAttribute(conv_mma_kernel<1024, 1>,
                         cudaFuncAttributeMaxDynamicSharedMemorySize, CONV_SMEM);
    cudaFuncSetAttribute(conv_mma_kernel<128, 0>,
                         cudaFuncAttributeMaxDynamicSharedMemorySize, CONV_SMEM);

    // prep: bf16 hi/lo splits + layout changes
    prep_w_kernel<<<512, 256>>>(w1, w1h, w1l, 1024);
    prep_w_kernel<<<512, 256>>>(w4, w4h, w4l, 1024);
    prep_w_kernel<<<64, 256>>>(w5, w5h, w5l, 128);
    {
        dim3 g(2, 32, 256), blk(32, 8);
        prep_x_kernel<<<g, blk>>>(low_key, xkh, xkl);
        prep_x_kernel<<<g, blk>>>(low_nonkey, xnh, xnl);
    }

    // conv1 + conv4 in one launch (256 CTAs)
    conv_mma_kernel<1024, 1><<<256, 256, CONV_SMEM>>>(
        xkh, xkl, w1h, w1l, y1, xnh, xnl, w4h, w4l, y4);

    bn_stats_kernel<<<128, 256>>>(y1, g1, b1, scale1, shift1);
    bn_stats_kernel<<<128, 256>>>(y4, g4, b4, scale4, shift4);

    dim3 tgrid(128, 4, 4), tblk(32, 8);
    bn_relu_transpose_kernel<<<tgrid, tblk>>>(y1, scale1, shift1, lk);
    bn_relu_transpose_kernel<<<tgrid, tblk>>>(y4, scale4, shift4, lnk);

    local_weight_kernel<<<16384, 128>>>(atten, lk, lnk, o0h, o0l);

    conv_mma_kernel<128, 0><<<128, 256, CONV_SMEM>>>(
        o0h, o0l, w5h, w5l, y5, o0h, o0l, w5h, w5l, y5);

    bn_stats_kernel<<<128, 256>>>(y5, g5, b5, scale5, shift5);
    pool_bn_relu_kernel<<<512, 256>>>(y5, scale5, shift5, pooled);
    fc_kernel<<<1, 64>>>(pooled, fc1w, fc1b, fc2w, fc2b, out);
}

// round 4
// speedup vs baseline: 2.6756x; 1.4182x over previous
#include <cuda_runtime.h>
#include <cuda_fp16.h>
#include <cstdint>

#define BN_EPS 1e-5f
#define WSCALE 512.f
#define INV_WSCALE (1.f / 512.f)

// ---------------- scratch (device globals; no allocation allowed) ----------
__device__ float g_y1[4 * 128 * 64 * 64];       // conv1 raw (NCHW)
__device__ float g_y4[4 * 128 * 64 * 64];       // conv4 raw (NCHW)
__device__ float g_y5[4 * 128 * 64 * 64];       // conv5 raw (NCHW)
__device__ float g_lk[4 * 64 * 64 * 128];       // BN+ReLU(conv1) NHWC fp32
__device__ float g_lnk[4 * 64 * 64 * 128];      // BN+ReLU(conv4) NHWC fp32
__device__ __half g_xk[4 * 64 * 64 * 1024];     // low_key NHWC fp16
__device__ __half g_xn[4 * 64 * 64 * 1024];     // low_nonkey NHWC fp16
__device__ __half g_w1_h[128 * 9216];           // [c][pos*1024+ci] * 512, hi
__device__ __half g_w1_l[128 * 9216];           // lo
__device__ __half g_w4_h[128 * 9216];
__device__ __half g_w4_l[128 * 9216];
__device__ __half g_w5_h[128 * 1152];
__device__ __half g_w5_l[128 * 1152];
__device__ __half g_o0[4 * 64 * 64 * 128];      // (trans - lnk) NHWC fp16
__device__ float g_scale[3][128];
__device__ float g_shift[3][128];
__device__ float g_pooled[4 * 128];

// ======================= PTX helpers (baseline ISA only) ====================
__device__ __forceinline__ uint32_t smem_u32(const void* p) {
    uint32_t a;
    asm("{ .reg .u64 t; cvta.to.shared.u64 t, %1; cvt.u32.u64 %0, t; }" : "=r"(a) : "l"(p));
    return a;
}
__device__ __forceinline__ void cp16(uint32_t dst, const void* src, int sz) {
    asm volatile("cp.async.cg.shared.global [%0], [%1], 16, %2;\n"
                 :: "r"(dst), "l"(src), "r"(sz));
}
__device__ __forceinline__ void ldsm_x4(uint32_t& r0, uint32_t& r1, uint32_t& r2,
                                        uint32_t& r3, uint32_t addr) {
    asm volatile("ldmatrix.sync.aligned.m8n8.x4.shared.b16 {%0,%1,%2,%3}, [%4];"
                 : "=r"(r0), "=r"(r1), "=r"(r2), "=r"(r3) : "r"(addr));
}
__device__ __forceinline__ void mma16816(float* d, const uint32_t* a, const uint32_t* b) {
    asm volatile(
        "mma.sync.aligned.m16n8k16.row.col.f32.f16.f16.f32 "
        "{%0,%1,%2,%3}, {%4,%5,%6,%7}, {%8,%9}, {%0,%1,%2,%3};"
        : "+f"(d[0]), "+f"(d[1]), "+f"(d[2]), "+f"(d[3])
        : "r"(a[0]), "r"(a[1]), "r"(a[2]), "r"(a[3]), "r"(b[0]), "r"(b[1]));
}

// ======================= conv GEMM (mma.sync fp16, 2-product w-split) =======
// CTA: M=128 (c_out) x N=256 pixels (4 rows x 64). K-chunk = 32 (one tap,
// 32 in-channels). Products: x*wh + x*wl (w pre-scaled by 512; x single fp16).
// 8 warps as 2(M) x 4(N): warp tile 64x64. Double buffered; PITCH=80
// (conflict-free ldmatrix). Stage: A_h[0,10240) A_l[10240,20480) B[20480,40960)
#define PITCH 80
#define STG_AL 10240
#define STG_B 20480
#define STAGE_SZ 40960

template <int CIN>
__device__ __forceinline__ void load_stage(
    uint32_t sb,
    const __half* __restrict__ wh, const __half* __restrict__ wl,
    const __half* __restrict__ x,
    int iter, int b, int h0, int tid)
{
    const int K = CIN * 9;
    int pos = iter % 9, cic = iter / 9;      // tap-minor for cross-CTA L2 reuse
    int kh = pos / 3, kw = pos - 3 * kh;
    int k0 = pos * CIN + cic * 32;

    // A: 128 rows x 64B x 2 halves = 1024 chunks of 16B; 4/thread
#pragma unroll
    for (int u = 0; u < 4; u++) {
        int idx = tid * 4 + u;
        int hl = idx >> 9, rem = idx & 511;
        int row = rem >> 2, c16 = rem & 3;
        const __half* src = (hl ? wl : wh) + row * K + k0 + c16 * 8;
        cp16(sb + hl * STG_AL + row * PITCH + c16 * 16, src, 16);
    }
    // B: 256 pixels x 64B = 1024 chunks; 4/thread
#pragma unroll
    for (int u = 0; u < 4; u++) {
        int idx = tid * 4 + u;
        int px = idx >> 2, c16 = idx & 3;
        int r = px >> 6, ww = px & 63;
        int y = h0 + r + kh - 1;
        int xw = ww + kw - 1;
        bool ok = ((unsigned)y < 64u) && ((unsigned)xw < 64u);
        int yc = ok ? y : 0, xc = ok ? xw : 0;
        const __half* src =
            x + ((size_t)((b * 64 + yc) * 64 + xc)) * CIN + cic * 32 + c16 * 8;
        cp16(sb + STG_B + px * PITCH + c16 * 16, src, ok ? 16 : 0);
    }
}

template <int CIN, int DUAL>
__global__ __launch_bounds__(256, 1) void conv_mma_kernel(
    const __half* __restrict__ x0,
    const __half* __restrict__ wh0, const __half* __restrict__ wl0,
    float* __restrict__ y0,
    const __half* __restrict__ x1,
    const __half* __restrict__ wh1, const __half* __restrict__ wl1,
    float* __restrict__ y1p)
{
    extern __shared__ char smem[];
    const uint32_t sbase = smem_u32(smem);
    const int tid = threadIdx.x;
    const int wid = tid >> 5;
    const int lane = tid & 31;

    int bx = blockIdx.x;
    int sel = DUAL ? (bx >> 6) : 0;
    int t = DUAL ? (bx & 63) : bx;
    int b = t >> 4;
    int h0 = (t & 15) * 4;

    const __half* x  = sel ? x1  : x0;
    const __half* wh = sel ? wh1 : wh0;
    const __half* wl = sel ? wl1 : wl0;
    float* y = sel ? y1p : y0;

    const int mi = wid & 1;     // M block: 64 rows
    const int ni = wid >> 1;    // N block: 64 pixels (one image row)
    const int m0 = mi * 64;
    const int n0 = ni * 64;

    float acc[4][8][4];
#pragma unroll
    for (int a = 0; a < 4; a++)
#pragma unroll
        for (int j = 0; j < 8; j++)
#pragma unroll
            for (int e = 0; e < 4; e++) acc[a][j][e] = 0.f;

    constexpr int NIT = 9 * (CIN / 32);
    const uint32_t stage0 = sbase;
    const uint32_t stage1 = sbase + STAGE_SZ;

    load_stage<CIN>(stage0, wh, wl, x, 0, b, h0, tid);
    asm volatile("cp.async.commit_group;" ::: "memory");
    load_stage<CIN>(stage1, wh, wl, x, 1, b, h0, tid);
    asm volatile("cp.async.commit_group;" ::: "memory");

    const uint32_t frag_off = (uint32_t)((lane & 15) * PITCH + (lane >> 4) * 16);

    for (int i = 0; i < NIT; i++) {
        uint32_t st = (i & 1) ? stage1 : stage0;

        if (i + 1 < NIT) asm volatile("cp.async.wait_group 1;" ::: "memory");
        else             asm volatile("cp.async.wait_group 0;" ::: "memory");
        __syncthreads();

#pragma unroll
        for (int s = 0; s < 2; s++) {   // two k16 steps in k-chunk 32
            uint32_t ah[4][4], al[4][4], bf[4][4];
#pragma unroll
            for (int tt = 0; tt < 4; tt++)
                ldsm_x4(ah[tt][0], ah[tt][1], ah[tt][2], ah[tt][3],
                        st + (m0 + tt * 16) * PITCH + s * 32 + frag_off);
#pragma unroll
            for (int tt = 0; tt < 4; tt++)
                ldsm_x4(al[tt][0], al[tt][1], al[tt][2], al[tt][3],
                        st + STG_AL + (m0 + tt * 16) * PITCH + s * 32 + frag_off);
#pragma unroll
            for (int q = 0; q < 4; q++)
                ldsm_x4(bf[q][0], bf[q][1], bf[q][2], bf[q][3],
                        st + STG_B + (n0 + q * 16) * PITCH + s * 32 + frag_off);
#pragma unroll
            for (int tt = 0; tt < 4; tt++)
#pragma unroll
                for (int q = 0; q < 4; q++) {
                    uint32_t b0[2] = { bf[q][0], bf[q][2] };   // n8 tile 0
                    uint32_t b1[2] = { bf[q][1], bf[q][3] };   // n8 tile 1
                    mma16816(acc[tt][q * 2 + 0], ah[tt], b0);
                    mma16816(acc[tt][q * 2 + 1], ah[tt], b1);
                    mma16816(acc[tt][q * 2 + 0], al[tt], b0);
                    mma16816(acc[tt][q * 2 + 1], al[tt], b1);
                }
        }
        __syncthreads();
        if (i + 2 < NIT) {
            load_stage<CIN>(st, wh, wl, x, i + 2, b, h0, tid);
            asm volatile("cp.async.commit_group;" ::: "memory");
        }
    }

    // epilogue: D frag: row = gid (+8), col = 2*tig (+1); scale by 1/512
    const int gid = lane >> 2;
    const int tig = lane & 3;
    const int hrow = h0 + ni;            // this warp's image row
#pragma unroll
    for (int tt = 0; tt < 4; tt++) {
        int r0 = m0 + tt * 16 + gid;
#pragma unroll
        for (int j = 0; j < 8; j++) {
            int col = j * 8 + tig * 2;
            float* d0 = y + (size_t)(b * 128 + r0) * 4096 + hrow * 64 + col;
            float* d1 = y + (size_t)(b * 128 + r0 + 8) * 4096 + hrow * 64 + col;
            float2 v0 = make_float2(acc[tt][j][0] * INV_WSCALE, acc[tt][j][1] * INV_WSCALE);
            float2 v1 = make_float2(acc[tt][j][2] * INV_WSCALE, acc[tt][j][3] * INV_WSCALE);
            *(float2*)d0 = v0;
            *(float2*)d1 = v1;
        }
    }
}

// ======================= prep kernels =======================================
// weights: [c_out][ci][kh][kw] -> [c_out][pos*CIN+ci] * 512, fp16 hi/lo split
__global__ void prep_w_kernel(const float* __restrict__ w,
                              __half* __restrict__ wh,
                              __half* __restrict__ wl, int CIN)
{
    int K = CIN * 9;
    int total = 128 * K;
    for (int i = blockIdx.x * blockDim.x + threadIdx.x; i < total;
         i += gridDim.x * blockDim.x) {
        int c = i / K, k = i - c * K;
        int pos = k / CIN, ci = k - pos * CIN;
        float v = w[(c * CIN + ci) * 9 + pos] * WSCALE;
        __half h = __float2half_rn(v);
        wh[i] = h;
        wl[i] = __float2half_rn(v - __half2float(h));
    }
}

// x: NCHW fp32 -> NHWC fp16
__global__ void prep_x_kernel(const float* __restrict__ x,
                              __half* __restrict__ xh)
{
    __shared__ float ttile[32][33];
    int bh = blockIdx.z;
    int b = bh >> 6, h = bh & 63;
    int ciT = blockIdx.y * 32, wT = blockIdx.x * 32;
    int tx = threadIdx.x, ty = threadIdx.y;
#pragma unroll
    for (int r = 0; r < 4; r++) {
        int ci = ciT + ty + r * 8;
        ttile[ty + r * 8][tx] = x[((size_t)(b * 1024 + ci) * 64 + h) * 64 + wT + tx];
    }
    __syncthreads();
#pragma unroll
    for (int r = 0; r < 4; r++) {
        int w = wT + ty + r * 8;
        float v = ttile[tx][ty + r * 8];
        size_t o = ((size_t)(b * 64 + h) * 64 + w) * 1024 + ciT + tx;
        xh[o] = __float2half_rn(v);
    }
}

// ======================= BN / elementwise chain =============================
__global__ void bn_stats_kernel(const float* __restrict__ y,
                                const float* __restrict__ gamma,
                                const float* __restrict__ beta,
                                float* __restrict__ scale,
                                float* __restrict__ shift)
{
    int c = blockIdx.x;
    int tid = threadIdx.x;
    float s = 0.f, s2 = 0.f;
    for (int b = 0; b < 4; b++) {
        const float4* p = (const float4*)(y + (size_t)(b * 128 + c) * 4096);
        for (int i = tid; i < 1024; i += 256) {
            float4 v = p[i];
            s  += v.x + v.y + v.z + v.w;
            s2 += v.x * v.x + v.y * v.y + v.z * v.z + v.w * v.w;
        }
    }
    __shared__ float sh[256], sh2[256];
    sh[tid] = s; sh2[tid] = s2;
    __syncthreads();
    for (int o = 128; o > 0; o >>= 1) {
        if (tid < o) { sh[tid] += sh[tid + o]; sh2[tid] += sh2[tid + o]; }
        __syncthreads();
    }
    if (tid == 0) {
        float mean = sh[0] * (1.f / 16384.f);
        float var  = sh2[0] * (1.f / 16384.f) - mean * mean;
        float sc = gamma[c] * rsqrtf(var + BN_EPS);
        scale[c] = sc;
        shift[c] = beta[c] - mean * sc;
    }
}

__global__ void bn_relu_transpose_kernel(const float* __restrict__ y,
                                         const float* __restrict__ scale,
                                         const float* __restrict__ shift,
                                         float* __restrict__ o)
{
    __shared__ float ttile[32][33];
    int b = blockIdx.z;
    int c0 = blockIdx.y * 32;
    int p0 = blockIdx.x * 32;
    int tx = threadIdx.x, ty = threadIdx.y;
#pragma unroll
    for (int r = 0; r < 4; r++) {
        int c = c0 + ty + r * 8;
        float v = y[(size_t)(b * 128 + c) * 4096 + p0 + tx];
        v = fmaxf(fmaf(v, scale[c], shift[c]), 0.f);
        ttile[ty + r * 8][tx] = v;
    }
    __syncthreads();
#pragma unroll
    for (int r = 0; r < 4; r++) {
        int p = p0 + ty + r * 8;
        o[(size_t)(b * 4096 + p) * 128 + c0 + tx] = ttile[tx][ty + r * 8];
    }
}

// local weighting + subtract lnk; output as NHWC fp16 (conv5 B operand)
__global__ __launch_bounds__(128) void local_weight_kernel(
    const float* __restrict__ atten,  // [B,H,W,81]
    const float* __restrict__ lk,     // NHWC fp32
    const float* __restrict__ lnk,    // NHWC fp32
    __half* __restrict__ o0)
{
    int bp = blockIdx.x;
    int b = bp >> 12;
    int p = bp & 4095;
    int h = p >> 6;
    int w = p & 63;

    __shared__ float att[81];
    if (threadIdx.x < 81) att[threadIdx.x] = atten[(size_t)bp * 81 + threadIdx.x];
    __syncthreads();

    int c = threadIdx.x;
    float acc = 0.f;
#pragma unroll
    for (int dh = 0; dh < 9; dh++) {
        int yy = h + dh - 4;
        if ((unsigned)yy >= 64u) continue;
        const float* row = lk + (size_t)((b * 64 + yy) * 64) * 128 + c;
#pragma unroll
        for (int dw = 0; dw < 9; dw++) {
            int xx = w + dw - 4;
            if ((unsigned)xx < 64u)
                acc = fmaf(att[dh * 9 + dw], row[(size_t)xx * 128], acc);
        }
    }
    float v = acc - lnk[(size_t)bp * 128 + c];
    o0[(size_t)bp * 128 + c] = __float2half_rn(v);
}

__global__ void pool_bn_relu_kernel(const float* __restrict__ y,
                                    const float* __restrict__ scale,
                                    const float* __restrict__ shift,
                                    float* __restrict__ pooled)
{
    int bc = blockIdx.x;
    int c = bc & 127;
    float sc = scale[c], sf = shift[c];
    const float* p = y + (size_t)bc * 4096;
    float s = 0.f;
    for (int i = threadIdx.x; i < 4096; i += 256)
        s += fmaxf(fmaf(p[i], sc, sf), 0.f);
    __shared__ float sh[256];
    sh[threadIdx.x] = s;
    __syncthreads();
    for (int o = 128; o > 0; o >>= 1) {
        if (threadIdx.x < o) sh[threadIdx.x] += sh[threadIdx.x + o];
        __syncthreads();
    }
    if (threadIdx.x == 0) pooled[bc] = sh[0] * (1.f / 4096.f);
}

__global__ void fc_kernel(const float* __restrict__ pooled,
                          const float* __restrict__ fc1w,
                          const float* __restrict__ fc1b,
                          const float* __restrict__ fc2w,
                          const float* __restrict__ fc2b,
                          float* __restrict__ out)
{
    __shared__ float hbuf[4][10];
    int tid = threadIdx.x;
    if (tid < 40) {
        int b = tid / 10, j = tid % 10;
        float s = fc1b[j];
        const float* wr = fc1w + j * 128;
        const float* pr = pooled + b * 128;
        for (int c = 0; c < 128; c++) s = fmaf(wr[c], pr[c], s);
        hbuf[b][j] = s;
    }
    __syncthreads();
    if (tid < 4) {
        float s = fc2b[0];
        for (int j = 0; j < 10; j++) s = fmaf(fc2w[j], hbuf[tid][j], s);
        out[tid] = s;
    }
}

// ======================= launch =============================================
extern "C" void kernel_launch(void* const* d_in, const int* in_sizes, int n_in,
                              void* d_out, int out_size)
{
    const float* low_key    = (const float*)d_in[0];
    const float* low_nonkey = (const float*)d_in[1];
    const float* atten      = (const float*)d_in[2];
    const float* w1 = (const float*)d_in[3];
    const float* g1 = (const float*)d_in[4];
    const float* b1 = (const float*)d_in[5];
    const float* w4 = (const float*)d_in[6];
    const float* g4 = (const float*)d_in[7];
    const float* b4 = (const float*)d_in[8];
    const float* w5 = (const float*)d_in[9];
    const float* g5 = (const float*)d_in[10];
    const float* b5 = (const float*)d_in[11];
    const float* fc1w = (const float*)d_in[12];
    const float* fc1b = (const float*)d_in[13];
    const float* fc2w = (const float*)d_in[14];
    const float* fc2b = (const float*)d_in[15];
    float* out = (float*)d_out;

    float *y1, *y4, *y5, *lk, *lnk, *scale, *shift, *pooled;
    __half *xk, *xn, *w1h, *w1l, *w4h, *w4l, *w5h, *w5l, *o0;
    cudaGetSymbolAddress((void**)&y1, g_y1);
    cudaGetSymbolAddress((void**)&y4, g_y4);
    cudaGetSymbolAddress((void**)&y5, g_y5);
    cudaGetSymbolAddress((void**)&lk, g_lk);
    cudaGetSymbolAddress((void**)&lnk, g_lnk);
    cudaGetSymbolAddress((void**)&xk, g_xk);
    cudaGetSymbolAddress((void**)&xn, g_xn);
    cudaGetSymbolAddress((void**)&w1h, g_w1_h);
    cudaGetSymbolAddress((void**)&w1l, g_w1_l);
    cudaGetSymbolAddress((void**)&w4h, g_w4_h);
    cudaGetSymbolAddress((void**)&w4l, g_w4_l);
    cudaGetSymbolAddress((void**)&w5h, g_w5_h);
    cudaGetSymbolAddress((void**)&w5l, g_w5_l);
    cudaGetSymbolAddress((void**)&o0, g_o0);
    cudaGetSymbolAddress((void**)&scale, g_scale);
    cudaGetSymbolAddress((void**)&shift, g_shift);
    cudaGetSymbolAddress((void**)&pooled, g_pooled);

    float* scale1 = scale + 0 * 128; float* shift1 = shift + 0 * 128;
    float* scale4 = scale + 1 * 128; float* shift4 = shift + 1 * 128;
    float* scale5 = scale + 2 * 128; float* shift5 = shift + 2 * 128;

    const int CONV_SMEM = 2 * STAGE_SZ;  // 81920
    cudaFuncSetAttribute(conv_mma_kernel<1024, 1>,
                         cudaFuncAttributeMaxDynamicSharedMemorySize, CONV_SMEM);
    cudaFuncSetAttribute(conv_mma_kernel<128, 0>,
                         cudaFuncAttributeMaxDynamicSharedMemorySize, CONV_SMEM);

    // prep: fp16 conversions + layout changes
    prep_w_kernel<<<512, 256>>>(w1, w1h, w1l, 1024);
    prep_w_kernel<<<512, 256>>>(w4, w4h, w4l, 1024);
    prep_w_kernel<<<64, 256>>>(w5, w5h, w5l, 128);
    {
        dim3 g(2, 32, 256), blk(32, 8);
        prep_x_kernel<<<g, blk>>>(low_key, xk);
        prep_x_kernel<<<g, blk>>>(low_nonkey, xn);
    }

    // conv1 + conv4 in one launch (128 CTAs = one wave)
    conv_mma_kernel<1024, 1><<<128, 256, CONV_SMEM>>>(
        xk, w1h, w1l, y1, xn, w4h, w4l, y4);

    bn_stats_kernel<<<128, 256>>>(y1, g1, b1, scale1, shift1);
    bn_stats_kernel<<<128, 256>>>(y4, g4, b4, scale4, shift4);

    dim3 tgrid(128, 4, 4), tblk(32, 8);
    bn_relu_transpose_kernel<<<tgrid, tblk>>>(y1, scale1, shift1, lk);
    bn_relu_transpose_kernel<<<tgrid, tblk>>>(y4, scale4, shift4, lnk);

    local_weight_kernel<<<16384, 128>>>(atten, lk, lnk, o0);

    conv_mma_kernel<128, 0><<<64, 256, CONV_SMEM>>>(
        o0, w5h, w5l, y5, o0, w5h, w5l, y5);

    bn_stats_kernel<<<128, 256>>>(y5, g5, b5, scale5, shift5);
    pool_bn_relu_kernel<<<512, 256>>>(y5, scale5, shift5, pooled);
    fc_kernel<<<1, 64>>>(pooled, fc1w, fc1b, fc2w, fc2b, out);
}

// round 5
// speedup vs baseline: 4.2828x; 1.6007x over previous
#include <cuda_runtime.h>
#include <cuda_fp16.h>
#include <cstdint>

#define BN_EPS 1e-5f

// ---------------- scratch (device globals; no allocation allowed) ----------
__device__ float g_y1[4 * 128 * 64 * 64];       // conv1 raw (NCHW)
__device__ float g_y4[4 * 128 * 64 * 64];       // conv4 raw (NCHW)
__device__ float g_y5[4 * 128 * 64 * 64];       // conv5 raw (NCHW)
__device__ __half g_lk[4 * 64 * 64 * 128];      // BN+ReLU(conv1) NHWC fp16
__device__ __half g_lnk[4 * 64 * 64 * 128];     // BN+ReLU(conv4) NHWC fp16
__device__ __half g_xk[4 * 64 * 64 * 1024];     // low_key NHWC fp16
__device__ __half g_xn[4 * 64 * 64 * 1024];     // low_nonkey NHWC fp16
__device__ __half g_w1[128 * 9216];             // [c][pos*1024+ci] fp16
__device__ __half g_w4[128 * 9216];
__device__ __half g_w5[128 * 1152];
__device__ __half g_o0[4 * 64 * 64 * 128];      // (trans - lnk) NHWC fp16
__device__ float g_scale[3][128];
__device__ float g_shift[3][128];
__device__ float g_pooled[4 * 128];

// ======================= PTX helpers (baseline ISA only) ====================
__device__ __forceinline__ uint32_t smem_u32(const void* p) {
    uint32_t a;
    asm("{ .reg .u64 t; cvta.to.shared.u64 t, %1; cvt.u32.u64 %0, t; }" : "=r"(a) : "l"(p));
    return a;
}
__device__ __forceinline__ void cp16(uint32_t dst, const void* src, int sz) {
    asm volatile("cp.async.cg.shared.global [%0], [%1], 16, %2;\n"
                 :: "r"(dst), "l"(src), "r"(sz));
}
__device__ __forceinline__ void ldsm_x4(uint32_t& r0, uint32_t& r1, uint32_t& r2,
                                        uint32_t& r3, uint32_t addr) {
    asm volatile("ldmatrix.sync.aligned.m8n8.x4.shared.b16 {%0,%1,%2,%3}, [%4];"
                 : "=r"(r0), "=r"(r1), "=r"(r2), "=r"(r3) : "r"(addr));
}
__device__ __forceinline__ void mma16816(float* d, const uint32_t* a, const uint32_t* b) {
    asm volatile(
        "mma.sync.aligned.m16n8k16.row.col.f32.f16.f16.f32 "
        "{%0,%1,%2,%3}, {%4,%5,%6,%7}, {%8,%9}, {%0,%1,%2,%3};"
        : "+f"(d[0]), "+f"(d[1]), "+f"(d[2]), "+f"(d[3])
        : "r"(a[0]), "r"(a[1]), "r"(a[2]), "r"(a[3]), "r"(b[0]), "r"(b[1]));
}

// ======================= conv GEMM (mma.sync fp16, single product) ==========
// CTA: M=128 (c_out) x N=256 pixels (4 rows x 64). K-chunk = 32 (one tap,
// 32 in-channels). 8 warps as 2(M) x 4(N): warp tile 64x64. Double buffered;
// PITCH=80 (conflict-free ldmatrix). Stage: A[0,10240) B[10240,30720)
#define PITCH 80
#define STG_B 10240
#define STAGE_SZ 30720

template <int CIN>
__device__ __forceinline__ void load_stage(
    uint32_t sb,
    const __half* __restrict__ w,
    const __half* __restrict__ x,
    int iter, int b, int h0, int tid)
{
    const int K = CIN * 9;
    int pos = iter % 9, cic = iter / 9;      // tap-minor for cross-CTA L2 reuse
    int kh = pos / 3, kw = pos - 3 * kh;
    int k0 = pos * CIN + cic * 32;

    // A: 128 rows x 64B = 512 chunks of 16B; 2/thread
#pragma unroll
    for (int u = 0; u < 2; u++) {
        int idx = tid * 2 + u;
        int row = idx >> 2, c16 = idx & 3;
        const __half* src = w + row * K + k0 + c16 * 8;
        cp16(sb + row * PITCH + c16 * 16, src, 16);
    }
    // B: 256 pixels x 64B = 1024 chunks; 4/thread
#pragma unroll
    for (int u = 0; u < 4; u++) {
        int idx = tid * 4 + u;
        int px = idx >> 2, c16 = idx & 3;
        int r = px >> 6, ww = px & 63;
        int y = h0 + r + kh - 1;
        int xw = ww + kw - 1;
        bool ok = ((unsigned)y < 64u) && ((unsigned)xw < 64u);
        int yc = ok ? y : 0, xc = ok ? xw : 0;
        const __half* src =
            x + ((size_t)((b * 64 + yc) * 64 + xc)) * CIN + cic * 32 + c16 * 8;
        cp16(sb + STG_B + px * PITCH + c16 * 16, src, ok ? 16 : 0);
    }
}

template <int CIN, int DUAL>
__global__ __launch_bounds__(256, 1) void conv_mma_kernel(
    const __half* __restrict__ x0, const __half* __restrict__ w0,
    float* __restrict__ y0,
    const __half* __restrict__ x1, const __half* __restrict__ w1,
    float* __restrict__ y1p)
{
    extern __shared__ char smem[];
    const uint32_t sbase = smem_u32(smem);
    const int tid = threadIdx.x;
    const int wid = tid >> 5;
    const int lane = tid & 31;

    int bx = blockIdx.x;
    int sel = DUAL ? (bx >> 6) : 0;
    int t = DUAL ? (bx & 63) : bx;
    int b = t >> 4;
    int h0 = (t & 15) * 4;

    const __half* x = sel ? x1 : x0;
    const __half* w = sel ? w1 : w0;
    float* y = sel ? y1p : y0;

    const int mi = wid & 1;     // M block: 64 rows
    const int ni = wid >> 1;    // N block: 64 pixels (one image row)
    const int m0 = mi * 64;
    const int n0 = ni * 64;

    float acc[4][8][4];
#pragma unroll
    for (int a = 0; a < 4; a++)
#pragma unroll
        for (int j = 0; j < 8; j++)
#pragma unroll
            for (int e = 0; e < 4; e++) acc[a][j][e] = 0.f;

    constexpr int NIT = 9 * (CIN / 32);
    const uint32_t stage0 = sbase;
    const uint32_t stage1 = sbase + STAGE_SZ;

    load_stage<CIN>(stage0, w, x, 0, b, h0, tid);
    asm volatile("cp.async.commit_group;" ::: "memory");
    load_stage<CIN>(stage1, w, x, 1, b, h0, tid);
    asm volatile("cp.async.commit_group;" ::: "memory");

    const uint32_t frag_off = (uint32_t)((lane & 15) * PITCH + (lane >> 4) * 16);

    for (int i = 0; i < NIT; i++) {
        uint32_t st = (i & 1) ? stage1 : stage0;

        if (i + 1 < NIT) asm volatile("cp.async.wait_group 1;" ::: "memory");
        else             asm volatile("cp.async.wait_group 0;" ::: "memory");
        __syncthreads();

#pragma unroll
        for (int s = 0; s < 2; s++) {   // two k16 steps in k-chunk 32
            uint32_t ah[4][4], bf[4][4];
#pragma unroll
            for (int tt = 0; tt < 4; tt++)
                ldsm_x4(ah[tt][0], ah[tt][1], ah[tt][2], ah[tt][3],
                        st + (m0 + tt * 16) * PITCH + s * 32 + frag_off);
#pragma unroll
            for (int q = 0; q < 4; q++)
                ldsm_x4(bf[q][0], bf[q][1], bf[q][2], bf[q][3],
                        st + STG_B + (n0 + q * 16) * PITCH + s * 32 + frag_off);
#pragma unroll
            for (int tt = 0; tt < 4; tt++)
#pragma unroll
                for (int q = 0; q < 4; q++) {
                    uint32_t b0[2] = { bf[q][0], bf[q][2] };   // n8 tile 0
                    uint32_t b1[2] = { bf[q][1], bf[q][3] };   // n8 tile 1
                    mma16816(acc[tt][q * 2 + 0], ah[tt], b0);
                    mma16816(acc[tt][q * 2 + 1], ah[tt], b1);
                }
        }
        __syncthreads();
        if (i + 2 < NIT) {
            load_stage<CIN>(st, w, x, i + 2, b, h0, tid);
            asm volatile("cp.async.commit_group;" ::: "memory");
        }
    }

    // epilogue: D frag: row = gid (+8), col = 2*tig (+1)
    const int gid = lane >> 2;
    const int tig = lane & 3;
    const int hrow = h0 + ni;            // this warp's image row
#pragma unroll
    for (int tt = 0; tt < 4; tt++) {
        int r0 = m0 + tt * 16 + gid;
#pragma unroll
        for (int j = 0; j < 8; j++) {
            int col = j * 8 + tig * 2;
            float* d0 = y + (size_t)(b * 128 + r0) * 4096 + hrow * 64 + col;
            float* d1 = y + (size_t)(b * 128 + r0 + 8) * 4096 + hrow * 64 + col;
            *(float2*)d0 = make_float2(acc[tt][j][0], acc[tt][j][1]);
            *(float2*)d1 = make_float2(acc[tt][j][2], acc[tt][j][3]);
        }
    }
}

// ======================= prep kernels =======================================
// weights: [c_out][ci][kh][kw] -> [c_out][pos*CIN+ci] fp16
__global__ void prep_w_kernel(const float* __restrict__ w,
                              __half* __restrict__ wo, int CIN)
{
    int K = CIN * 9;
    int total = 128 * K;
    for (int i = blockIdx.x * blockDim.x + threadIdx.x; i < total;
         i += gridDim.x * blockDim.x) {
        int c = i / K, k = i - c * K;
        int pos = k / CIN, ci = k - pos * CIN;
        wo[i] = __float2half_rn(w[(c * CIN + ci) * 9 + pos]);
    }
}

// x: NCHW fp32 -> NHWC fp16
__global__ void prep_x_kernel(const float* __restrict__ x,
                              __half* __restrict__ xh)
{
    __shared__ float ttile[32][33];
    int bh = blockIdx.z;
    int b = bh >> 6, h = bh & 63;
    int ciT = blockIdx.y * 32, wT = blockIdx.x * 32;
    int tx = threadIdx.x, ty = threadIdx.y;
#pragma unroll
    for (int r = 0; r < 4; r++) {
        int ci = ciT + ty + r * 8;
        ttile[ty + r * 8][tx] = x[((size_t)(b * 1024 + ci) * 64 + h) * 64 + wT + tx];
    }
    __syncthreads();
#pragma unroll
    for (int r = 0; r < 4; r++) {
        int w = wT + ty + r * 8;
        float v = ttile[tx][ty + r * 8];
        size_t o = ((size_t)(b * 64 + h) * 64 + w) * 1024 + ciT + tx;
        xh[o] = __float2half_rn(v);
    }
}

// ======================= BN / elementwise chain =============================
__global__ void bn_stats_kernel(const float* __restrict__ y,
                                const float* __restrict__ gamma,
                                const float* __restrict__ beta,
                                float* __restrict__ scale,
                                float* __restrict__ shift)
{
    int c = blockIdx.x;
    int tid = threadIdx.x;
    float s = 0.f, s2 = 0.f;
    for (int b = 0; b < 4; b++) {
        const float4* p = (const float4*)(y + (size_t)(b * 128 + c) * 4096);
        for (int i = tid; i < 1024; i += 256) {
            float4 v = p[i];
            s  += v.x + v.y + v.z + v.w;
            s2 += v.x * v.x + v.y * v.y + v.z * v.z + v.w * v.w;
        }
    }
    __shared__ float sh[256], sh2[256];
    sh[tid] = s; sh2[tid] = s2;
    __syncthreads();
    for (int o = 128; o > 0; o >>= 1) {
        if (tid < o) { sh[tid] += sh[tid + o]; sh2[tid] += sh2[tid + o]; }
        __syncthreads();
    }
    if (tid == 0) {
        float mean = sh[0] * (1.f / 16384.f);
        float var  = sh2[0] * (1.f / 16384.f) - mean * mean;
        float sc = gamma[c] * rsqrtf(var + BN_EPS);
        scale[c] = sc;
        shift[c] = beta[c] - mean * sc;
    }
}

// BN + ReLU + NCHW fp32 -> NHWC fp16
__global__ void bn_relu_transpose_kernel(const float* __restrict__ y,
                                         const float* __restrict__ scale,
                                         const float* __restrict__ shift,
                                         __half* __restrict__ o)
{
    __shared__ float ttile[32][33];
    int b = blockIdx.z;
    int c0 = blockIdx.y * 32;
    int p0 = blockIdx.x * 32;
    int tx = threadIdx.x, ty = threadIdx.y;
#pragma unroll
    for (int r = 0; r < 4; r++) {
        int c = c0 + ty + r * 8;
        float v = y[(size_t)(b * 128 + c) * 4096 + p0 + tx];
        v = fmaxf(fmaf(v, scale[c], shift[c]), 0.f);
        ttile[ty + r * 8][tx] = v;
    }
    __syncthreads();
#pragma unroll
    for (int r = 0; r < 4; r++) {
        int p = p0 + ty + r * 8;
        o[(size_t)(b * 4096 + p) * 128 + c0 + tx] =
            __float2half_rn(ttile[tx][ty + r * 8]);
    }
}

// local weighting + subtract lnk; 2 pixels per block, half2 per thread
__global__ __launch_bounds__(128) void local_weight_kernel(
    const float* __restrict__ atten,  // [B,H,W,81]
    const __half* __restrict__ lk,    // NHWC fp16
    const __half* __restrict__ lnk,   // NHWC fp16
    __half* __restrict__ o0)          // NHWC fp16
{
    int bp0 = blockIdx.x * 2;
    __shared__ float att[2][81];
    for (int i = threadIdx.x; i < 162; i += 128)
        att[i / 81][i - (i / 81) * 81] = atten[(size_t)bp0 * 81 + i];
    __syncthreads();

    int px = threadIdx.x >> 6;        // 0..1
    int c2 = threadIdx.x & 63;        // half2 lane (2 channels)
    int bp = bp0 + px;
    int b = bp >> 12;
    int p = bp & 4095;
    int h = p >> 6;
    int w = p & 63;

    float2 acc = make_float2(0.f, 0.f);
#pragma unroll
    for (int dh = 0; dh < 9; dh++) {
        int yy = h + dh - 4;
        if ((unsigned)yy >= 64u) continue;
        const __half2* row =
            (const __half2*)(lk + (size_t)((b * 64 + yy) * 64) * 128) + c2;
#pragma unroll
        for (int dw = 0; dw < 9; dw++) {
            int xx = w + dw - 4;
            if ((unsigned)xx < 64u) {
                float2 v = __half22float2(row[(size_t)xx * 64]);
                float a = att[px][dh * 9 + dw];
                acc.x = fmaf(a, v.x, acc.x);
                acc.y = fmaf(a, v.y, acc.y);
            }
        }
    }
    float2 l = __half22float2(((const __half2*)(lnk + (size_t)bp * 128))[c2]);
    ((__half2*)(o0 + (size_t)bp * 128))[c2] =
        __floats2half2_rn(acc.x - l.x, acc.y - l.y);
}

__global__ void pool_bn_relu_kernel(const float* __restrict__ y,
                                    const float* __restrict__ scale,
                                    const float* __restrict__ shift,
                                    float* __restrict__ pooled)
{
    int bc = blockIdx.x;
    int c = bc & 127;
    float sc = scale[c], sf = shift[c];
    const float* p = y + (size_t)bc * 4096;
    float s = 0.f;
    for (int i = threadIdx.x; i < 4096; i += 256)
        s += fmaxf(fmaf(p[i], sc, sf), 0.f);
    __shared__ float sh[256];
    sh[threadIdx.x] = s;
    __syncthreads();
    for (int o = 128; o > 0; o >>= 1) {
        if (threadIdx.x < o) sh[threadIdx.x] += sh[threadIdx.x + o];
        __syncthreads();
    }
    if (threadIdx.x == 0) pooled[bc] = sh[0] * (1.f / 4096.f);
}

__global__ void fc_kernel(const float* __restrict__ pooled,
                          const float* __restrict__ fc1w,
                          const float* __restrict__ fc1b,
                          const float* __restrict__ fc2w,
                          const float* __restrict__ fc2b,
                          float* __restrict__ out)
{
    __shared__ float hbuf[4][10];
    int tid = threadIdx.x;
    if (tid < 40) {
        int b = tid / 10, j = tid % 10;
        float s = fc1b[j];
        const float* wr = fc1w + j * 128;
        const float* pr = pooled + b * 128;
        for (int c = 0; c < 128; c++) s = fmaf(wr[c], pr[c], s);
        hbuf[b][j] = s;
    }
    __syncthreads();
    if (tid < 4) {
        float s = fc2b[0];
        for (int j = 0; j < 10; j++) s = fmaf(fc2w[j], hbuf[tid][j], s);
        out[tid] = s;
    }
}

// ======================= launch =============================================
extern "C" void kernel_launch(void* const* d_in, const int* in_sizes, int n_in,
                              void* d_out, int out_size)
{
    const float* low_key    = (const float*)d_in[0];
    const float* low_nonkey = (const float*)d_in[1];
    const float* atten      = (const float*)d_in[2];
    const float* w1 = (const float*)d_in[3];
    const float* g1 = (const float*)d_in[4];
    const float* b1 = (const float*)d_in[5];
    const float* w4 = (const float*)d_in[6];
    const float* g4 = (const float*)d_in[7];
    const float* b4 = (const float*)d_in[8];
    const float* w5 = (const float*)d_in[9];
    const float* g5 = (const float*)d_in[10];
    const float* b5 = (const float*)d_in[11];
    const float* fc1w = (const float*)d_in[12];
    const float* fc1b = (const float*)d_in[13];
    const float* fc2w = (const float*)d_in[14];
    const float* fc2b = (const float*)d_in[15];
    float* out = (float*)d_out;

    float *y1, *y4, *y5, *scale, *shift, *pooled;
    __half *lk, *lnk, *xk, *xn, *pw1, *pw4, *pw5, *o0;
    cudaGetSymbolAddress((void**)&y1, g_y1);
    cudaGetSymbolAddress((void**)&y4, g_y4);
    cudaGetSymbolAddress((void**)&y5, g_y5);
    cudaGetSymbolAddress((void**)&lk, g_lk);
    cudaGetSymbolAddress((void**)&lnk, g_lnk);
    cudaGetSymbolAddress((void**)&xk, g_xk);
    cudaGetSymbolAddress((void**)&xn, g_xn);
    cudaGetSymbolAddress((void**)&pw1, g_w1);
    cudaGetSymbolAddress((void**)&pw4, g_w4);
    cudaGetSymbolAddress((void**)&pw5, g_w5);
    cudaGetSymbolAddress((void**)&o0, g_o0);
    cudaGetSymbolAddress((void**)&scale, g_scale);
    cudaGetSymbolAddress((void**)&shift, g_shift);
    cudaGetSymbolAddress((void**)&pooled, g_pooled);

    float* scale1 = scale + 0 * 128; float* shift1 = shift + 0 * 128;
    float* scale4 = scale + 1 * 128; float* shift4 = shift + 1 * 128;
    float* scale5 = scale + 2 * 128; float* shift5 = shift + 2 * 128;

    const int CONV_SMEM = 2 * STAGE_SZ;  // 61440
    cudaFuncSetAttribute(conv_mma_kernel<1024, 1>,
                         cudaFuncAttributeMaxDynamicSharedMemorySize, CONV_SMEM);
    cudaFuncSetAttribute(conv_mma_kernel<128, 0>,
                         cudaFuncAttributeMaxDynamicSharedMemorySize, CONV_SMEM);

    // prep: fp16 conversions + layout changes
    prep_w_kernel<<<512, 256>>>(w1, pw1, 1024);
    prep_w_kernel<<<512, 256>>>(w4, pw4, 1024);
    prep_w_kernel<<<64, 256>>>(w5, pw5, 128);
    {
        dim3 g(2, 32, 256), blk(32, 8);
        prep_x_kernel<<<g, blk>>>(low_key, xk);
        prep_x_kernel<<<g, blk>>>(low_nonkey, xn);
    }

    // conv1 + conv4 in one launch (128 CTAs = one wave)
    conv_mma_kernel<1024, 1><<<128, 256, CONV_SMEM>>>(
        xk, pw1, y1, xn, pw4, y4);

    bn_stats_kernel<<<128, 256>>>(y1, g1, b1, scale1, shift1);
    bn_stats_kernel<<<128, 256>>>(y4, g4, b4, scale4, shift4);

    dim3 tgrid(128, 4, 4), tblk(32, 8);
    bn_relu_transpose_kernel<<<tgrid, tblk>>>(y1, scale1, shift1, lk);
    bn_relu_transpose_kernel<<<tgrid, tblk>>>(y4, scale4, shift4, lnk);

    local_weight_kernel<<<8192, 128>>>(atten, lk, lnk, o0);

    conv_mma_kernel<128, 0><<<64, 256, CONV_SMEM>>>(
        o0, pw5, y5, o0, pw5, y5);

    bn_stats_kernel<<<128, 256>>>(y5, g5, b5, scale5, shift5);
    pool_bn_relu_kernel<<<512, 256>>>(y5, scale5, shift5, pooled);
    fc_kernel<<<1, 64>>>(pooled, fc1w, fc1b, fc2w, fc2b, out);
}